// round 8
// baseline (speedup 1.0000x reference)
#include <cuda_runtime.h>

#define BSZ   8
#define NPTS  4096
#define CIN   128
#define COUT  256
#define MCTR  1024
#define SSAMP 64

#define GEMM_BLOCKS 1024                 // (NPTS/64)*(COUT/128)*BSZ
#define MP_CHUNK    8                    // centers per consumer block
#define MP_BLOCKS   (BSZ * MCTR / MP_CHUNK)   // 1024

// Scratch (static device globals: no allocations allowed)
__device__ float g_pre[BSZ * NPTS * COUT];   // [b][n][o]  33.5 MB
__device__ int   g_fps[BSZ * MCTR];
__device__ int   g_prog[BSZ];                // FPS progress (valid g_fps count)
__device__ int   g_done;                     // retired GEMM blocks

// Exact reference arithmetic: squares then left-to-right sum, no FMA contraction.
__device__ __forceinline__ float d2_rn(float ax, float ay, float az,
                                       float bx, float by, float bz) {
    float dx = ax - bx, dy = ay - by, dz = az - bz;
    return __fadd_rn(__fadd_rn(__fmul_rn(dx, dx), __fmul_rn(dy, dy)),
                     __fmul_rn(dz, dz));
}

// ---- packed f32x2 helpers (per-lane IEEE rn: bit-identical to scalar) ----
__device__ __forceinline__ unsigned long long pack2(float lo, float hi) {
    unsigned long long r;
    asm("mov.b64 %0, {%1, %2};" : "=l"(r) : "f"(lo), "f"(hi));
    return r;
}
__device__ __forceinline__ void unpack2(unsigned long long v, float& lo, float& hi) {
    asm("mov.b64 {%0, %1}, %2;" : "=f"(lo), "=f"(hi) : "l"(v));
}
__device__ __forceinline__ unsigned long long add2(unsigned long long a,
                                                   unsigned long long b) {
    unsigned long long r;
    asm("add.rn.f32x2 %0, %1, %2;" : "=l"(r) : "l"(a), "l"(b));
    return r;
}
__device__ __forceinline__ unsigned long long mul2(unsigned long long a,
                                                   unsigned long long b) {
    unsigned long long r;
    asm("mul.rn.f32x2 %0, %1, %2;" : "=l"(r) : "l"(a), "l"(b));
    return r;
}

// ---- release/acquire helpers (single-writer progress publication) ----
__device__ __forceinline__ void st_rel(int* p, int v) {
    asm volatile("st.release.gpu.global.s32 [%0], %1;" :: "l"(p), "r"(v) : "memory");
}
__device__ __forceinline__ int ld_acq(const int* p) {
    int v;
    asm volatile("ld.acquire.gpu.global.s32 %0, [%1];" : "=r"(v) : "l"(p) : "memory");
    return v;
}

// ---------------------------------------------------------------------------
// Reset kernel: zero the cross-replay-persistent flags before the fused run.
// ---------------------------------------------------------------------------
__global__ void reset_kernel() {
    if (threadIdx.x < BSZ) g_prog[threadIdx.x] = 0;
    if (threadIdx.x == 0)  g_done = 0;
}

// ---------------------------------------------------------------------------
// FPS (blocks 0..7): 512 threads x 8 points, packed f32x2, REDUX argmax.
// Tail trim: the unique owner lane prefetches the winner's coords from xyz
// (L1-resident) BEFORE the barrier, overlapping the barrier wait.
// Publishes progress with st.release.gpu each iteration (single writer).
// Arithmetic bit-identical to rounds 4-7 (dx = px + (-lx) == px - lx).
// ---------------------------------------------------------------------------
__device__ void fps_body(const float* __restrict__ xyz, int b) {
    const int tid = threadIdx.x;
    const int lane = tid & 31, warp = tid >> 5;   // 16 warps

    __shared__ int    s_val[2][16];
    __shared__ int    s_key[2][16];
    __shared__ float4 s_cc[2][16];

    const float* p = xyz + b * NPTS * 3;

    unsigned long long px2[4], py2[4], pz2[4];
    float mind[8];
#pragma unroll
    for (int j = 0; j < 4; j++) {
        int n0 = (2 * j) * 512 + tid;
        int n1 = (2 * j + 1) * 512 + tid;
        px2[j] = pack2(p[3 * n0 + 0], p[3 * n1 + 0]);
        py2[j] = pack2(p[3 * n0 + 1], p[3 * n1 + 1]);
        pz2[j] = pack2(p[3 * n0 + 2], p[3 * n1 + 2]);
        mind[2 * j] = 1e10f; mind[2 * j + 1] = 1e10f;
    }
    float cx = __ldg(p + 0), cy = __ldg(p + 1), cz = __ldg(p + 2);
    if (tid == 0) {
        g_fps[b * MCTR] = 0;
        st_rel(&g_prog[b], 1);
    }

    for (int t = 1; t < MCTR; t++) {
        const unsigned long long nlx2 = pack2(-cx, -cx);
        const unsigned long long nly2 = pack2(-cy, -cy);
        const unsigned long long nlz2 = pack2(-cz, -cz);

#pragma unroll
        for (int j = 0; j < 4; j++) {
            unsigned long long dx2 = add2(px2[j], nlx2);
            unsigned long long dy2 = add2(py2[j], nly2);
            unsigned long long dz2 = add2(pz2[j], nlz2);
            unsigned long long s2 = add2(add2(mul2(dx2, dx2), mul2(dy2, dy2)),
                                         mul2(dz2, dz2));
            float s0, s1; unpack2(s2, s0, s1);
            mind[2 * j]     = fminf(mind[2 * j],     s0);
            mind[2 * j + 1] = fminf(mind[2 * j + 1], s1);
        }

        // scalar max tree (all values >= 0 -> int bit order == value order)
        float m01 = fmaxf(mind[0], mind[1]), m23 = fmaxf(mind[2], mind[3]);
        float m45 = fmaxf(mind[4], mind[5]), m67 = fmaxf(mind[6], mind[7]);
        float best = fmaxf(fmaxf(m01, m23), fmaxf(m45, m67));

        const int tb   = __float_as_int(best);
        const int wmax = __reduce_max_sync(0xffffffffu, tb);

        int n = 0x7fffffff;
        if (tb == wmax) {   // rare; descending k -> lowest point index
#pragma unroll
            for (int k = 7; k >= 0; k--)
                if (__float_as_int(mind[k]) == wmax) n = k * 512 + tid;
        }
        const int widx = __reduce_min_sync(0xffffffffu, n);

        if (n == widx) {    // unique owner lane: prefetch coords pre-barrier
            float ox = __ldg(p + 3 * widx + 0);
            float oy = __ldg(p + 3 * widx + 1);
            float oz = __ldg(p + 3 * widx + 2);
            s_cc[t & 1][warp] = make_float4(ox, oy, oz, 0.0f);
        }
        if (lane == 0) {
            s_val[t & 1][warp] = wmax;
            s_key[t & 1][warp] = (widx << 4) | warp;   // widx<4096 fits
        }
        __syncthreads();

        int vb = (lane < 16) ? s_val[t & 1][lane] : (int)0x80000000;
        int vk = (lane < 16) ? s_key[t & 1][lane] : 0x7fffffff;
        const int bmax = __reduce_max_sync(0xffffffffu, vb);
        int cand = (vb == bmax) ? vk : 0x7fffffff;
        const int kmin = __reduce_min_sync(0xffffffffu, cand);
        const int Iv = kmin >> 4, ww = kmin & 15;
        float4 cc = s_cc[t & 1][ww];    // uniform broadcast LDS.128
        cx = cc.x; cy = cc.y; cz = cc.z;

        if (tid == 0) {
            g_fps[b * MCTR + t] = Iv;
            st_rel(&g_prog[b], t + 1);
        }
    }
}

// ---------------------------------------------------------------------------
// GEMM (blocks 8..1031): pre[b][n][o] = sum_c feat[b][c][n] * W[o][c].
// Tile 64n x 128o, K-chunks of 32, 2x8 microtile, 512 threads.
// Signals completion via g_done.
// ---------------------------------------------------------------------------
__device__ void gemm_body(const float* __restrict__ feat,
                          const float* __restrict__ W, int gid) {
    const int b    = gid >> 7;
    const int rest = gid & 127;
    const int o0   = (rest & 1) * 128;
    const int n0   = (rest >> 1) * 64;

    __shared__ float sF[32][66];
    __shared__ float sW[32][132];

    const int tid = threadIdx.x;
    const int tx = tid & 31;
    const int ty = tid >> 5;

    float acc[2][8];
#pragma unroll
    for (int i = 0; i < 2; i++)
#pragma unroll
        for (int j = 0; j < 8; j++) acc[i][j] = 0.f;

    const float* fb = feat + b * CIN * NPTS;

    for (int k0 = 0; k0 < CIN; k0 += 32) {
#pragma unroll
        for (int i = 0; i < 4; i++) {
            int e = tid + i * 512;
            sF[e >> 6][e & 63] = fb[(k0 + (e >> 6)) * NPTS + n0 + (e & 63)];
        }
#pragma unroll
        for (int i = 0; i < 8; i++) {
            int e = tid + i * 512;
            sW[e & 31][e >> 5] = W[(o0 + (e >> 5)) * CIN + k0 + (e & 31)];
        }
        __syncthreads();
#pragma unroll
        for (int c = 0; c < 32; c++) {
            float fv0 = sF[c][tx * 2 + 0];
            float fv1 = sF[c][tx * 2 + 1];
            float wv[8];
#pragma unroll
            for (int j = 0; j < 8; j++) wv[j] = sW[c][ty * 8 + j];
#pragma unroll
            for (int j = 0; j < 8; j++) {
                acc[0][j] += fv0 * wv[j];
                acc[1][j] += fv1 * wv[j];
            }
        }
        __syncthreads();
    }

    float* pb = g_pre + b * NPTS * COUT;
#pragma unroll
    for (int i = 0; i < 2; i++) {
        int n = n0 + tx * 2 + i;
#pragma unroll
        for (int j = 0; j < 8; j++)
            pb[n * COUT + o0 + ty * 8 + j] = acc[i][j];
    }

    __syncthreads();
    __threadfence();
    if (tid == 0) atomicAdd(&g_done, 1);
}

// ---------------------------------------------------------------------------
// Consumer (blocks 1032..2055): ballquery + max-gather + BN/ReLU for
// MP_CHUNK=8 consecutive centers of one batch. Gated on GEMM completion and
// FPS progress; neighbor lists live in shared memory only.
// g_fps read via __ldcg (L2) to avoid stale L1 lines across blocks.
// ---------------------------------------------------------------------------
__device__ void bqmp_body(const float* __restrict__ xyz,
                          const float* __restrict__ bconv,
                          const float* __restrict__ gamma,
                          const float* __restrict__ beta,
                          const float* __restrict__ rmean,
                          const float* __restrict__ rvar,
                          float* __restrict__ out, int gid) {
    const int b  = gid >> 7;
    const int m0 = (gid & 127) * MP_CHUNK;
    const int tid = threadIdx.x;

    __shared__ int s_nbr[MP_CHUNK][SSAMP];   // COUT-premultiplied offsets

    if (tid == 0) {
        while (ld_acq(&g_done) < GEMM_BLOCKS) __nanosleep(256);
        while (ld_acq(&g_prog[b]) < m0 + MP_CHUNK) __nanosleep(128);
    }
    __syncthreads();

    const int c = tid >> 6, ctid = tid & 63;   // center-in-chunk, thread-in-center
    const int m = m0 + c;
    const float* p = xyz + b * NPTS * 3;

    // --- ballquery: one warp per center (bit-exact r1 semantics) ---
    if (ctid < 32) {
        const int lane = ctid;
        const int ci = __ldcg(&g_fps[b * MCTR + m]);
        const float cx = p[3 * ci + 0], cy = p[3 * ci + 1], cz = p[3 * ci + 2];
        const float R2 = 0.1024f;

        int cnt = 0, firstIdx = 0;
        for (int c0 = 0; c0 < NPTS && cnt < SSAMP; c0 += 32) {
            int n = c0 + lane;
            float d = d2_rn(p[3 * n + 0], p[3 * n + 1], p[3 * n + 2], cx, cy, cz);
            bool in = d < R2;
            unsigned msk = __ballot_sync(0xffffffffu, in);
            if (cnt == 0 && msk) firstIdx = c0 + (__ffs(msk) - 1);
            if (in) {
                int pos = cnt + __popc(msk & ((1u << lane) - 1u));
                if (pos < SSAMP) s_nbr[c][pos] = n * COUT;
            }
            cnt += __popc(msk);
        }
        for (int pos = cnt + lane; pos < SSAMP; pos += 32)
            s_nbr[c][pos] = firstIdx * COUT;
    }
    __syncthreads();

    // --- max-gather + folded BN/bias/ReLU: 64 threads x float4 per center ---
    const float* pb = g_pre + b * NPTS * COUT + ctid * 4;
    float4 mx = make_float4(-3.4e38f, -3.4e38f, -3.4e38f, -3.4e38f);
#pragma unroll 8
    for (int s = 0; s < SSAMP; s++) {
        const float4 v = *(const float4*)(pb + s_nbr[c][s]);
        mx.x = fmaxf(mx.x, v.x); mx.y = fmaxf(mx.y, v.y);
        mx.z = fmaxf(mx.z, v.z); mx.w = fmaxf(mx.w, v.w);
    }

    const float4 bc = ((const float4*)bconv)[ctid];
    const float4 gm = ((const float4*)gamma)[ctid];
    const float4 bt = ((const float4*)beta )[ctid];
    const float4 rm = ((const float4*)rmean)[ctid];
    const float4 rv = ((const float4*)rvar )[ctid];

    const int o = ctid * 4;
    out[(b * COUT + o + 0) * MCTR + m] =
        fmaxf((mx.x + bc.x - rm.x) * (gm.x * rsqrtf(rv.x + 1e-5f)) + bt.x, 0.f);
    out[(b * COUT + o + 1) * MCTR + m] =
        fmaxf((mx.y + bc.y - rm.y) * (gm.y * rsqrtf(rv.y + 1e-5f)) + bt.y, 0.f);
    out[(b * COUT + o + 2) * MCTR + m] =
        fmaxf((mx.z + bc.z - rm.z) * (gm.z * rsqrtf(rv.z + 1e-5f)) + bt.z, 0.f);
    out[(b * COUT + o + 3) * MCTR + m] =
        fmaxf((mx.w + bc.w - rm.w) * (gm.w * rsqrtf(rv.w + 1e-5f)) + bt.w, 0.f);
}

// ---------------------------------------------------------------------------
// One fused launch: 8 FPS blocks + 1024 GEMM blocks + 1024 consumer blocks.
// Consumers pipeline against FPS via acquire/release progress flags.
// ---------------------------------------------------------------------------
__global__ __launch_bounds__(512) void fused_kernel(
    const float* __restrict__ xyz,  const float* __restrict__ feat,
    const float* __restrict__ W,    const float* __restrict__ bconv,
    const float* __restrict__ gamma,const float* __restrict__ beta,
    const float* __restrict__ rmean,const float* __restrict__ rvar,
    float* __restrict__ out) {
    const int bid = blockIdx.x;
    if (bid < BSZ) {
        fps_body(xyz, bid);
    } else if (bid < BSZ + GEMM_BLOCKS) {
        gemm_body(feat, W, bid - BSZ);
    } else {
        bqmp_body(xyz, bconv, gamma, beta, rmean, rvar, out,
                  bid - BSZ - GEMM_BLOCKS);
    }
}

// ---------------------------------------------------------------------------
extern "C" void kernel_launch(void* const* d_in, const int* in_sizes, int n_in,
                              void* d_out, int out_size) {
    const float* xyz  = (const float*)d_in[0];
    const float* feat = (const float*)d_in[1];
    const float* W    = (const float*)d_in[2];
    const float* bcv  = (const float*)d_in[3];
    const float* gm   = (const float*)d_in[4];
    const float* bt   = (const float*)d_in[5];
    const float* rm   = (const float*)d_in[6];
    const float* rv   = (const float*)d_in[7];
    float* out = (float*)d_out;

    reset_kernel<<<1, 32>>>();
    fused_kernel<<<BSZ + GEMM_BLOCKS + MP_BLOCKS, 512>>>(
        xyz, feat, W, bcv, gm, bt, rm, rv, out);
}

// round 9
// speedup vs baseline: 1.5668x; 1.5668x over previous
#include <cuda_runtime.h>

#define BSZ   8
#define NPTS  4096
#define CIN   128
#define COUT  256
#define MCTR  1024
#define SSAMP 64

// Scratch (static device globals: no allocations allowed)
__device__ float g_pre[BSZ * NPTS * COUT];   // [b][n][o]  33.5 MB
__device__ int   g_fps[BSZ * MCTR];

// Exact reference arithmetic: squares then left-to-right sum, no FMA contraction.
__device__ __forceinline__ float d2_rn(float ax, float ay, float az,
                                       float bx, float by, float bz) {
    float dx = ax - bx, dy = ay - by, dz = az - bz;
    return __fadd_rn(__fadd_rn(__fmul_rn(dx, dx), __fmul_rn(dy, dy)),
                     __fmul_rn(dz, dz));
}

// ---- packed f32x2 helpers (per-lane IEEE rn: bit-identical to scalar) ----
__device__ __forceinline__ unsigned long long pack2(float lo, float hi) {
    unsigned long long r;
    asm("mov.b64 %0, {%1, %2};" : "=l"(r) : "f"(lo), "f"(hi));
    return r;
}
__device__ __forceinline__ void unpack2(unsigned long long v, float& lo, float& hi) {
    asm("mov.b64 {%0, %1}, %2;" : "=f"(lo), "=f"(hi) : "l"(v));
}
__device__ __forceinline__ unsigned long long add2(unsigned long long a,
                                                   unsigned long long b) {
    unsigned long long r;
    asm("add.rn.f32x2 %0, %1, %2;" : "=l"(r) : "l"(a), "l"(b));
    return r;
}
__device__ __forceinline__ unsigned long long mul2(unsigned long long a,
                                                   unsigned long long b) {
    unsigned long long r;
    asm("mul.rn.f32x2 %0, %1, %2;" : "=l"(r) : "l"(a), "l"(b));
    return r;
}

// ---------------------------------------------------------------------------
// FPS (blocks 0..7): 256 threads x 16 points (8 packed f32x2 pairs).
// Tail (single barrier): warp REDUX(value); predicated lowest-index rescan;
// REDUX(min idx); the unique owner lane prefetches winner coords from xyz
// (L1-resident) BEFORE the barrier; lane 0 stores (val, key=(idx<<3)|warp);
// after ONE __syncthreads every warp redundantly REDUXes the 8 winners and
// reads the winning warp's coords with a uniform LDS.128.
// Arithmetic bit-identical to rounds 4-8 (dx = px + (-lx) == px - lx).
// ---------------------------------------------------------------------------
__device__ void fps_body(const float* __restrict__ xyz, int b) {
    const int tid = threadIdx.x;
    const int lane = tid & 31, warp = tid >> 5;   // 8 warps

    __shared__ int    s_val[2][8];
    __shared__ int    s_key[2][8];
    __shared__ float4 s_cc[2][8];

    const float* p = xyz + b * NPTS * 3;

    unsigned long long px2[8], py2[8], pz2[8];
    float mind[16];
#pragma unroll
    for (int j = 0; j < 8; j++) {
        int n0 = (2 * j) * 256 + tid;
        int n1 = (2 * j + 1) * 256 + tid;
        px2[j] = pack2(p[3 * n0 + 0], p[3 * n1 + 0]);
        py2[j] = pack2(p[3 * n0 + 1], p[3 * n1 + 1]);
        pz2[j] = pack2(p[3 * n0 + 2], p[3 * n1 + 2]);
        mind[2 * j] = 1e10f; mind[2 * j + 1] = 1e10f;
    }
    float cx = __ldg(p + 0), cy = __ldg(p + 1), cz = __ldg(p + 2);
    if (tid == 0) g_fps[b * MCTR] = 0;

    for (int t = 1; t < MCTR; t++) {
        const unsigned long long nlx2 = pack2(-cx, -cx);
        const unsigned long long nly2 = pack2(-cy, -cy);
        const unsigned long long nlz2 = pack2(-cz, -cz);

#pragma unroll
        for (int j = 0; j < 8; j++) {
            unsigned long long dx2 = add2(px2[j], nlx2);
            unsigned long long dy2 = add2(py2[j], nly2);
            unsigned long long dz2 = add2(pz2[j], nlz2);
            unsigned long long s2 = add2(add2(mul2(dx2, dx2), mul2(dy2, dy2)),
                                         mul2(dz2, dz2));
            float s0, s1; unpack2(s2, s0, s1);
            mind[2 * j]     = fminf(mind[2 * j],     s0);
            mind[2 * j + 1] = fminf(mind[2 * j + 1], s1);
        }

        // scalar max tree (all values >= 0 -> int bit order == value order)
        float m01 = fmaxf(mind[0], mind[1]),   m23 = fmaxf(mind[2], mind[3]);
        float m45 = fmaxf(mind[4], mind[5]),   m67 = fmaxf(mind[6], mind[7]);
        float m89 = fmaxf(mind[8], mind[9]),   mab = fmaxf(mind[10], mind[11]);
        float mcd = fmaxf(mind[12], mind[13]), mef = fmaxf(mind[14], mind[15]);
        float q0 = fmaxf(m01, m23), q1 = fmaxf(m45, m67);
        float q2 = fmaxf(m89, mab), q3 = fmaxf(mcd, mef);
        float best = fmaxf(fmaxf(q0, q1), fmaxf(q2, q3));

        const int tb   = __float_as_int(best);
        const int wmax = __reduce_max_sync(0xffffffffu, tb);

        int n = 0x7fffffff;
        if (tb == wmax) {   // rare; descending k -> lowest point index
#pragma unroll
            for (int k = 15; k >= 0; k--)
                if (__float_as_int(mind[k]) == wmax) n = k * 256 + tid;
        }
        const int widx = __reduce_min_sync(0xffffffffu, n);

        if (n == widx) {    // unique owner lane: prefetch coords pre-barrier
            float ox = __ldg(p + 3 * widx + 0);
            float oy = __ldg(p + 3 * widx + 1);
            float oz = __ldg(p + 3 * widx + 2);
            s_cc[t & 1][warp] = make_float4(ox, oy, oz, 0.0f);
        }
        if (lane == 0) {
            s_val[t & 1][warp] = wmax;
            s_key[t & 1][warp] = (widx << 3) | warp;   // widx<4096 fits
        }
        __syncthreads();

        int vb = (lane < 8) ? s_val[t & 1][lane] : (int)0x80000000;
        int vk = (lane < 8) ? s_key[t & 1][lane] : 0x7fffffff;
        const int bmax = __reduce_max_sync(0xffffffffu, vb);
        int cand = (vb == bmax) ? vk : 0x7fffffff;
        const int kmin = __reduce_min_sync(0xffffffffu, cand);
        const int Iv = kmin >> 3, ww = kmin & 7;
        float4 cc = s_cc[t & 1][ww];    // uniform broadcast LDS.128
        cx = cc.x; cy = cc.y; cz = cc.z;

        if (tid == 0) g_fps[b * MCTR + t] = Iv;
    }
}

// ---------------------------------------------------------------------------
// GEMM body (r5 champion, 256 threads): pre[b][n][o] = sum_c feat[b][c][n]*W[o][c].
// Tile 64n x 128o, K-chunks of 32, 4x8 microtile.
// ---------------------------------------------------------------------------
__device__ void gemm_body(const float* __restrict__ feat,
                          const float* __restrict__ W, int gid) {
    const int b    = gid >> 7;
    const int rest = gid & 127;
    const int o0   = (rest & 1) * 128;
    const int n0   = (rest >> 1) * 64;

    __shared__ float sF[32][65];
    __shared__ float sW[32][129];

    const int tid = threadIdx.x;
    const int tx = tid & 15;
    const int ty = tid >> 4;

    float acc[4][8];
#pragma unroll
    for (int i = 0; i < 4; i++)
#pragma unroll
        for (int j = 0; j < 8; j++) acc[i][j] = 0.f;

    const float* fb = feat + b * CIN * NPTS;

    for (int k0 = 0; k0 < CIN; k0 += 32) {
#pragma unroll
        for (int i = 0; i < 8; i++) {
            int e = tid + i * 256;
            sF[e >> 6][e & 63] = fb[(k0 + (e >> 6)) * NPTS + n0 + (e & 63)];
        }
#pragma unroll
        for (int i = 0; i < 16; i++) {
            int e = tid + i * 256;
            sW[e & 31][e >> 5] = W[(o0 + (e >> 5)) * CIN + k0 + (e & 31)];
        }
        __syncthreads();
#pragma unroll
        for (int c = 0; c < 32; c++) {
            float fv[4], wv[8];
#pragma unroll
            for (int i = 0; i < 4; i++) fv[i] = sF[c][tx * 4 + i];
#pragma unroll
            for (int j = 0; j < 8; j++) wv[j] = sW[c][ty * 8 + j];
#pragma unroll
            for (int i = 0; i < 4; i++)
#pragma unroll
                for (int j = 0; j < 8; j++) acc[i][j] += fv[i] * wv[j];
        }
        __syncthreads();
    }

    float* pb = g_pre + b * NPTS * COUT;
#pragma unroll
    for (int i = 0; i < 4; i++) {
        int n = n0 + tx * 4 + i;
#pragma unroll
        for (int j = 0; j < 8; j++)
            pb[n * COUT + o0 + ty * 8 + j] = acc[i][j];
    }
}

// ---------------------------------------------------------------------------
// Fused launch: blocks 0..7 -> FPS, blocks 8..1031 -> GEMM (hidden under FPS).
// ---------------------------------------------------------------------------
__global__ __launch_bounds__(256) void fused_fps_gemm_kernel(
    const float* __restrict__ xyz, const float* __restrict__ feat,
    const float* __restrict__ W) {
    if (blockIdx.x < BSZ) fps_body(xyz, blockIdx.x);
    else                  gemm_body(feat, W, blockIdx.x - BSZ);
}

// ---------------------------------------------------------------------------
// Fused ballquery + max-gather + BN/ReLU: one block (64 threads) per center.
// Warp 0 ball-queries (ballot-ordered ascending, early exit, pad-with-first)
// into smem; then all 64 threads max-gather float4 columns of g_pre.
// ---------------------------------------------------------------------------
__global__ __launch_bounds__(64) void bqmp_kernel(
    const float* __restrict__ xyz,
    const float* __restrict__ bconv, const float* __restrict__ gamma,
    const float* __restrict__ beta,  const float* __restrict__ rmean,
    const float* __restrict__ rvar,  float* __restrict__ out) {
    const int m = blockIdx.x, b = blockIdx.y, tid = threadIdx.x;
    const float* p = xyz + b * NPTS * 3;

    __shared__ int soff[SSAMP];   // COUT-premultiplied neighbor offsets

    if (tid < 32) {
        const int lane = tid;
        const int ci = g_fps[b * MCTR + m];
        const float cx = p[3 * ci + 0], cy = p[3 * ci + 1], cz = p[3 * ci + 2];
        const float R2 = 0.1024f;

        int cnt = 0, firstIdx = 0;
        for (int c0 = 0; c0 < NPTS && cnt < SSAMP; c0 += 32) {
            int n = c0 + lane;
            float d = d2_rn(p[3 * n + 0], p[3 * n + 1], p[3 * n + 2], cx, cy, cz);
            bool in = d < R2;
            unsigned msk = __ballot_sync(0xffffffffu, in);
            if (cnt == 0 && msk) firstIdx = c0 + (__ffs(msk) - 1);
            if (in) {
                int pos = cnt + __popc(msk & ((1u << lane) - 1u));
                if (pos < SSAMP) soff[pos] = n * COUT;
            }
            cnt += __popc(msk);
        }
        for (int pos = cnt + lane; pos < SSAMP; pos += 32)
            soff[pos] = firstIdx * COUT;
    }
    __syncthreads();

    const float* pb = g_pre + b * NPTS * COUT + tid * 4;
    float4 mx = make_float4(-3.4e38f, -3.4e38f, -3.4e38f, -3.4e38f);
#pragma unroll 8
    for (int s = 0; s < SSAMP; s++) {
        const float4 v = *(const float4*)(pb + soff[s]);
        mx.x = fmaxf(mx.x, v.x); mx.y = fmaxf(mx.y, v.y);
        mx.z = fmaxf(mx.z, v.z); mx.w = fmaxf(mx.w, v.w);
    }

    const float4 bc = ((const float4*)bconv)[tid];
    const float4 gm = ((const float4*)gamma)[tid];
    const float4 bt = ((const float4*)beta )[tid];
    const float4 rm = ((const float4*)rmean)[tid];
    const float4 rv = ((const float4*)rvar )[tid];

    const int o = tid * 4;
    out[(b * COUT + o + 0) * MCTR + m] =
        fmaxf((mx.x + bc.x - rm.x) * (gm.x * rsqrtf(rv.x + 1e-5f)) + bt.x, 0.f);
    out[(b * COUT + o + 1) * MCTR + m] =
        fmaxf((mx.y + bc.y - rm.y) * (gm.y * rsqrtf(rv.y + 1e-5f)) + bt.y, 0.f);
    out[(b * COUT + o + 2) * MCTR + m] =
        fmaxf((mx.z + bc.z - rm.z) * (gm.z * rsqrtf(rv.z + 1e-5f)) + bt.z, 0.f);
    out[(b * COUT + o + 3) * MCTR + m] =
        fmaxf((mx.w + bc.w - rm.w) * (gm.w * rsqrtf(rv.w + 1e-5f)) + bt.w, 0.f);
}

// ---------------------------------------------------------------------------
extern "C" void kernel_launch(void* const* d_in, const int* in_sizes, int n_in,
                              void* d_out, int out_size) {
    const float* xyz  = (const float*)d_in[0];
    const float* feat = (const float*)d_in[1];
    const float* W    = (const float*)d_in[2];
    const float* bcv  = (const float*)d_in[3];
    const float* gm   = (const float*)d_in[4];
    const float* bt   = (const float*)d_in[5];
    const float* rm   = (const float*)d_in[6];
    const float* rv   = (const float*)d_in[7];
    float* out = (float*)d_out;

    const int gemm_blocks = (NPTS / 64) * (COUT / 128) * BSZ;  // 1024
    fused_fps_gemm_kernel<<<BSZ + gemm_blocks, 256>>>(xyz, feat, W);
    bqmp_kernel<<<dim3(MCTR, BSZ), 64>>>(xyz, bcv, gm, bt, rm, rv, out);
}

// round 10
// speedup vs baseline: 1.7838x; 1.1385x over previous
#include <cuda_runtime.h>

#define BSZ   8
#define NPTS  4096
#define CIN   128
#define COUT  256
#define MCTR  1024
#define SSAMP 64
#define NTILES 1024     // (NPTS/64)*(COUT/128)*BSZ

// Scratch (static device globals: no allocations allowed)
__device__ float g_pre[BSZ * NPTS * COUT];   // [b][n][o]  33.5 MB
__device__ int   g_fps[BSZ * MCTR];
__device__ int   g_idx[BSZ * MCTR * SSAMP];
__device__ int   g_smid[BSZ];                // SMs hosting FPS blocks
__device__ int   g_ready;                    // FPS blocks that published smid
__device__ int   g_tile;                     // GEMM tile work queue head

// Exact reference arithmetic: squares then left-to-right sum, no FMA contraction.
__device__ __forceinline__ float d2_rn(float ax, float ay, float az,
                                       float bx, float by, float bz) {
    float dx = ax - bx, dy = ay - by, dz = az - bz;
    return __fadd_rn(__fadd_rn(__fmul_rn(dx, dx), __fmul_rn(dy, dy)),
                     __fmul_rn(dz, dz));
}

// ---- packed f32x2 helpers (per-lane IEEE rn: bit-identical to scalar) ----
__device__ __forceinline__ unsigned long long pack2(float lo, float hi) {
    unsigned long long r;
    asm("mov.b64 %0, {%1, %2};" : "=l"(r) : "f"(lo), "f"(hi));
    return r;
}
__device__ __forceinline__ void unpack2(unsigned long long v, float& lo, float& hi) {
    asm("mov.b64 {%0, %1}, %2;" : "=f"(lo), "=f"(hi) : "l"(v));
}
__device__ __forceinline__ unsigned long long add2(unsigned long long a,
                                                   unsigned long long b) {
    unsigned long long r;
    asm("add.rn.f32x2 %0, %1, %2;" : "=l"(r) : "l"(a), "l"(b));
    return r;
}
__device__ __forceinline__ unsigned long long mul2(unsigned long long a,
                                                   unsigned long long b) {
    unsigned long long r;
    asm("mul.rn.f32x2 %0, %1, %2;" : "=l"(r) : "l"(a), "l"(b));
    return r;
}

__device__ __forceinline__ void st_rel(int* p, int v) {
    asm volatile("st.release.gpu.global.s32 [%0], %1;" :: "l"(p), "r"(v) : "memory");
}
__device__ __forceinline__ int ld_acq(const int* p) {
    int v;
    asm volatile("ld.acquire.gpu.global.s32 %0, [%1];" : "=r"(v) : "l"(p) : "memory");
    return v;
}
__device__ __forceinline__ int my_smid() {
    int s; asm("mov.u32 %0, %%smid;" : "=r"(s)); return s;
}

// ---------------------------------------------------------------------------
__global__ void reset_kernel() {
    if (threadIdx.x == 0) { g_ready = 0; g_tile = 0; }
}

// ---------------------------------------------------------------------------
// FPS (r5 champion, verbatim): 256 threads x 16 points, packed f32x2 bulk,
// REDUX argmax with parity double-buffered warp winners, ONE barrier/iter.
// Publishes its %smid at start so GEMM blocks can avoid these SMs.
// ---------------------------------------------------------------------------
__device__ void fps_body(const float* __restrict__ xyz, int b) {
    const int tid = threadIdx.x;
    const int lane = tid & 31, warp = tid >> 5;

    __shared__ int s_wv[8];
    __shared__ int s_widx[2];

    if (tid == 0) {
        g_smid[b] = my_smid();
        __threadfence();
        atomicAdd(&g_ready, 1);
    }

    const float* p = xyz + b * NPTS * 3;

    unsigned long long px2[8], py2[8], pz2[8];
    float mind[16];
#pragma unroll
    for (int j = 0; j < 8; j++) {
        int n0 = (2 * j) * 256 + tid;
        int n1 = (2 * j + 1) * 256 + tid;
        px2[j] = pack2(p[3 * n0 + 0], p[3 * n1 + 0]);
        py2[j] = pack2(p[3 * n0 + 1], p[3 * n1 + 1]);
        pz2[j] = pack2(p[3 * n0 + 2], p[3 * n1 + 2]);
        mind[2 * j] = 1e10f; mind[2 * j + 1] = 1e10f;
    }
    if (tid == 0) s_widx[0] = 0;   // idx[0] = 0
    __syncthreads();

    for (int t = 1; t < MCTR; t++) {
        const int Iv = s_widx[(t - 1) & 1];
        if (tid == 0) {
            g_fps[b * MCTR + t - 1] = Iv;
            s_widx[t & 1] = 0x7fffffff;
        }
        const float lx = __ldg(p + 3 * Iv + 0);
        const float ly = __ldg(p + 3 * Iv + 1);
        const float lz = __ldg(p + 3 * Iv + 2);
        const unsigned long long nlx2 = pack2(-lx, -lx);
        const unsigned long long nly2 = pack2(-ly, -ly);
        const unsigned long long nlz2 = pack2(-lz, -lz);

#pragma unroll
        for (int j = 0; j < 8; j++) {
            unsigned long long dx2 = add2(px2[j], nlx2);
            unsigned long long dy2 = add2(py2[j], nly2);
            unsigned long long dz2 = add2(pz2[j], nlz2);
            unsigned long long s2 = add2(add2(mul2(dx2, dx2), mul2(dy2, dy2)),
                                         mul2(dz2, dz2));
            float s0, s1; unpack2(s2, s0, s1);
            mind[2 * j]     = fminf(mind[2 * j],     s0);
            mind[2 * j + 1] = fminf(mind[2 * j + 1], s1);
        }

        float m01 = fmaxf(mind[0], mind[1]),   m23 = fmaxf(mind[2], mind[3]);
        float m45 = fmaxf(mind[4], mind[5]),   m67 = fmaxf(mind[6], mind[7]);
        float m89 = fmaxf(mind[8], mind[9]),   mab = fmaxf(mind[10], mind[11]);
        float mcd = fmaxf(mind[12], mind[13]), mef = fmaxf(mind[14], mind[15]);
        float q0 = fmaxf(m01, m23), q1 = fmaxf(m45, m67);
        float q2 = fmaxf(m89, mab), q3 = fmaxf(mcd, mef);
        float best = fmaxf(fmaxf(q0, q1), fmaxf(q2, q3));

        const int tb   = __float_as_int(best);
        const int wmax = __reduce_max_sync(0xffffffffu, tb);
        if (lane == 0) s_wv[warp] = wmax;
        __syncthreads();

        int vb = (lane < 8) ? s_wv[lane] : (int)0x80000000;
        const int bmax = __reduce_max_sync(0xffffffffu, vb);

        if (tb == bmax) {  // rare: winner thread(s) resolve lowest index
            int n = 0x7fffffff;
#pragma unroll
            for (int k = 15; k >= 0; k--)
                if (__float_as_int(mind[k]) == bmax) n = k * 256 + tid;
            atomicMin(&s_widx[t & 1], n);
        }
        __syncthreads();
    }
    if (tid == 0) g_fps[b * MCTR + MCTR - 1] = s_widx[(MCTR - 1) & 1];
}

// ---------------------------------------------------------------------------
// One GEMM tile (r5 champion): pre[b][n][o] = sum_c feat[b][c][n] * W[o][c].
// Tile 64n x 128o, K-chunks of 32, 4x8 microtile, 256 threads.
// ---------------------------------------------------------------------------
__device__ void gemm_tile(const float* __restrict__ feat,
                          const float* __restrict__ W, int gid,
                          float sF[32][65], float sW[32][129]) {
    const int b    = gid >> 7;
    const int rest = gid & 127;
    const int o0   = (rest & 1) * 128;
    const int n0   = (rest >> 1) * 64;

    const int tid = threadIdx.x;
    const int tx = tid & 15;
    const int ty = tid >> 4;

    float acc[4][8];
#pragma unroll
    for (int i = 0; i < 4; i++)
#pragma unroll
        for (int j = 0; j < 8; j++) acc[i][j] = 0.f;

    const float* fb = feat + b * CIN * NPTS;

    for (int k0 = 0; k0 < CIN; k0 += 32) {
#pragma unroll
        for (int i = 0; i < 8; i++) {
            int e = tid + i * 256;
            sF[e >> 6][e & 63] = fb[(k0 + (e >> 6)) * NPTS + n0 + (e & 63)];
        }
#pragma unroll
        for (int i = 0; i < 16; i++) {
            int e = tid + i * 256;
            sW[e & 31][e >> 5] = W[(o0 + (e >> 5)) * CIN + k0 + (e & 31)];
        }
        __syncthreads();
#pragma unroll
        for (int c = 0; c < 32; c++) {
            float fv[4], wv[8];
#pragma unroll
            for (int i = 0; i < 4; i++) fv[i] = sF[c][tx * 4 + i];
#pragma unroll
            for (int j = 0; j < 8; j++) wv[j] = sW[c][ty * 8 + j];
#pragma unroll
            for (int i = 0; i < 4; i++)
#pragma unroll
                for (int j = 0; j < 8; j++) acc[i][j] += fv[i] * wv[j];
        }
        __syncthreads();
    }

    float* pb = g_pre + b * NPTS * COUT;
#pragma unroll
    for (int i = 0; i < 4; i++) {
        int n = n0 + tx * 4 + i;
#pragma unroll
        for (int j = 0; j < 8; j++)
            pb[n * COUT + o0 + ty * 8 + j] = acc[i][j];
    }
}

// ---------------------------------------------------------------------------
// GEMM worker: wait for the 8 FPS smids, exit if co-resident with FPS,
// otherwise drain the tile queue (loop-pop: completeness never depends on
// how many blocks exit).
// ---------------------------------------------------------------------------
__device__ void gemm_worker(const float* __restrict__ feat,
                            const float* __restrict__ W) {
    __shared__ float sF[32][65];
    __shared__ float sW[32][129];
    __shared__ int   s_go;       // 0 = exit (FPS SM), 1 = work
    __shared__ int   s_tile;

    const int tid = threadIdx.x;
    if (tid == 0) {
        while (ld_acq(&g_ready) < BSZ) __nanosleep(64);
        int sm = my_smid(), hit = 0;
#pragma unroll
        for (int i = 0; i < BSZ; i++) hit |= (g_smid[i] == sm);
        s_go = !hit;
    }
    __syncthreads();
    if (!s_go) return;           // keep FPS SMs free of GEMM work

    for (;;) {
        if (tid == 0) s_tile = atomicAdd(&g_tile, 1);
        __syncthreads();
        const int t = s_tile;
        if (t >= NTILES) return;
        gemm_tile(feat, W, t, sF, sW);
        __syncthreads();
    }
}

// ---------------------------------------------------------------------------
__global__ __launch_bounds__(256) void fused_fps_gemm_kernel(
    const float* __restrict__ xyz, const float* __restrict__ feat,
    const float* __restrict__ W) {
    if (blockIdx.x < BSZ) fps_body(xyz, blockIdx.x);
    else                  gemm_worker(feat, W);
}

// ---------------------------------------------------------------------------
// Ball query (r5 verbatim): one warp per (b,m) center.
// ---------------------------------------------------------------------------
__global__ __launch_bounds__(256) void ballquery_kernel(const float* __restrict__ xyz) {
    const int tid = threadIdx.x, lane = tid & 31, w = tid >> 5;
    const int gw = blockIdx.x * 8 + w;
    const int b = gw >> 10, m = gw & (MCTR - 1);
    const float* p = xyz + b * NPTS * 3;

    const int ci = g_fps[b * MCTR + m];
    const float cx = p[3 * ci + 0], cy = p[3 * ci + 1], cz = p[3 * ci + 2];
    const float R2 = 0.1024f;

    int cnt = 0, firstIdx = 0;
    int* dst = g_idx + (b * MCTR + m) * SSAMP;

    for (int c0 = 0; c0 < NPTS && cnt < SSAMP; c0 += 32) {
        int n = c0 + lane;
        float d = d2_rn(p[3 * n + 0], p[3 * n + 1], p[3 * n + 2], cx, cy, cz);
        bool in = d < R2;
        unsigned msk = __ballot_sync(0xffffffffu, in);
        if (cnt == 0 && msk) firstIdx = c0 + (__ffs(msk) - 1);
        if (in) {
            int pos = cnt + __popc(msk & ((1u << lane) - 1u));
            if (pos < SSAMP) dst[pos] = n;
        }
        cnt += __popc(msk);
    }
    for (int pos = cnt + lane; pos < SSAMP; pos += 32) dst[pos] = firstIdx;
}

// ---------------------------------------------------------------------------
// Max-gather + folded BN/bias/ReLU (r5 verbatim): 64 threads, float4/thread.
// ---------------------------------------------------------------------------
__global__ __launch_bounds__(64) void maxpool_kernel(
    const float* __restrict__ bconv, const float* __restrict__ gamma,
    const float* __restrict__ beta,  const float* __restrict__ rmean,
    const float* __restrict__ rvar,  float* __restrict__ out) {
    const int m = blockIdx.x, b = blockIdx.y, tid = threadIdx.x;

    __shared__ int soff[SSAMP];
    soff[tid] = g_idx[(b * MCTR + m) * SSAMP + tid] * COUT;
    __syncthreads();

    const float* pb = g_pre + b * NPTS * COUT + tid * 4;
    float4 mx = make_float4(-3.4e38f, -3.4e38f, -3.4e38f, -3.4e38f);
#pragma unroll 8
    for (int s = 0; s < SSAMP; s++) {
        const float4 v = *(const float4*)(pb + soff[s]);
        mx.x = fmaxf(mx.x, v.x); mx.y = fmaxf(mx.y, v.y);
        mx.z = fmaxf(mx.z, v.z); mx.w = fmaxf(mx.w, v.w);
    }

    const float4 bc = ((const float4*)bconv)[tid];
    const float4 gm = ((const float4*)gamma)[tid];
    const float4 bt = ((const float4*)beta )[tid];
    const float4 rm = ((const float4*)rmean)[tid];
    const float4 rv = ((const float4*)rvar )[tid];

    const int o = tid * 4;
    out[(b * COUT + o + 0) * MCTR + m] =
        fmaxf((mx.x + bc.x - rm.x) * (gm.x * rsqrtf(rv.x + 1e-5f)) + bt.x, 0.f);
    out[(b * COUT + o + 1) * MCTR + m] =
        fmaxf((mx.y + bc.y - rm.y) * (gm.y * rsqrtf(rv.y + 1e-5f)) + bt.y, 0.f);
    out[(b * COUT + o + 2) * MCTR + m] =
        fmaxf((mx.z + bc.z - rm.z) * (gm.z * rsqrtf(rv.z + 1e-5f)) + bt.z, 0.f);
    out[(b * COUT + o + 3) * MCTR + m] =
        fmaxf((mx.w + bc.w - rm.w) * (gm.w * rsqrtf(rv.w + 1e-5f)) + bt.w, 0.f);
}

// ---------------------------------------------------------------------------
extern "C" void kernel_launch(void* const* d_in, const int* in_sizes, int n_in,
                              void* d_out, int out_size) {
    const float* xyz  = (const float*)d_in[0];
    const float* feat = (const float*)d_in[1];
    const float* W    = (const float*)d_in[2];
    const float* bcv  = (const float*)d_in[3];
    const float* gm   = (const float*)d_in[4];
    const float* bt   = (const float*)d_in[5];
    const float* rm   = (const float*)d_in[6];
    const float* rv   = (const float*)d_in[7];
    float* out = (float*)d_out;

    reset_kernel<<<1, 32>>>();
    fused_fps_gemm_kernel<<<BSZ + NTILES, 256>>>(xyz, feat, W);
    ballquery_kernel<<<(BSZ * MCTR) / 8, 256>>>(xyz);
    maxpool_kernel<<<dim3(MCTR, BSZ), 64>>>(bcv, gm, bt, rm, rv, out);
}